// round 16
// baseline (speedup 1.0000x reference)
#include <cuda_runtime.h>
#include <cuda_bf16.h>
#include <math.h>

#define BS   8
#define SEQ  512
#define C    512
#define NC   5
#define H    768
#define W    768
#define HW   (H*W)
#define NTOK (BS*SEQ)          // 4096

#define THREADS 256
#define GRID    (NTOK / 8)     // 512 blocks, 8 warps = 8 tokens each

// Scratch (no allocations allowed)
__device__ float g_nll[NTOK];
__device__ int   g_msk[NTOK];
__device__ int   g_ctr;        // zero-init; reset at end of each run

// ---------------------------------------------------------------------------
// ONE kernel, one warp per token (best measured shape):
//   - mask!=1 tokens (~50%) skip GEMV + box scan entirely      [R14]
//   - box scan over ALIGNED 4-PIXEL GROUPS: one float4 per channel covers
//     4 pixels in 5 loads (was 20 scalar loads); x2 unroll -> 10 wide
//     independent loads in flight (~5KB/warp). Edge pixels rejected
//     per-component -> counts bit-identical.                   [NEW]
//   - logits[5] via warp GEMV (Wc staged in shared)
//   - first-max tiebreaks identical to jnp.argmax / bincount().argmax()
//   - last block does the deterministic fixed-order final reduction
// ---------------------------------------------------------------------------
__global__ __launch_bounds__(THREADS)
void token_kernel(const float* __restrict__ cl,
                  const float* __restrict__ fuse,
                  const float* __restrict__ Wc,
                  const float* __restrict__ bc,
                  const int*   __restrict__ coords,
                  const int*   __restrict__ mask,
                  float* __restrict__ out) {
    __shared__ float sW[NC * C];                 // 10 KB
    for (int i = threadIdx.x; i < NC * C; i += THREADS)
        sW[i] = Wc[i];
    __syncthreads();

    const int warp = threadIdx.x >> 5;
    const int lane = threadIdx.x & 31;
    const int t = blockIdx.x * 8 + warp;         // token id
    const int b = t / SEQ;

    const int m = mask[t];
    if (m == 1) {
        // ---- logits (warp GEMV, float4) ----
        const float4* fe4 = reinterpret_cast<const float4*>(fuse + (size_t)t * C);
        const float4* sW4 = reinterpret_cast<const float4*>(sW);
        float acc0=0.f, acc1=0.f, acc2=0.f, acc3=0.f, acc4=0.f;
#pragma unroll
        for (int i = lane; i < C/4; i += 32) {
            float4 e  = fe4[i];
            float4 w0 = sW4[0*(C/4) + i];
            float4 w1 = sW4[1*(C/4) + i];
            float4 w2 = sW4[2*(C/4) + i];
            float4 w3 = sW4[3*(C/4) + i];
            float4 w4 = sW4[4*(C/4) + i];
            acc0 += e.x*w0.x + e.y*w0.y + e.z*w0.z + e.w*w0.w;
            acc1 += e.x*w1.x + e.y*w1.y + e.z*w1.z + e.w*w1.w;
            acc2 += e.x*w2.x + e.y*w2.y + e.z*w2.z + e.w*w2.w;
            acc3 += e.x*w3.x + e.y*w3.y + e.z*w3.z + e.w*w3.w;
            acc4 += e.x*w4.x + e.y*w4.y + e.z*w4.z + e.w*w4.w;
        }
#pragma unroll
        for (int off = 16; off; off >>= 1) {
            acc0 += __shfl_xor_sync(0xffffffffu, acc0, off);
            acc1 += __shfl_xor_sync(0xffffffffu, acc1, off);
            acc2 += __shfl_xor_sync(0xffffffffu, acc2, off);
            acc3 += __shfl_xor_sync(0xffffffffu, acc3, off);
            acc4 += __shfl_xor_sync(0xffffffffu, acc4, off);
        }

        // ---- box scan: aligned float4 groups (4 px / 5 loads), x2 unroll ----
        const int4 cbox = *reinterpret_cast<const int4*>(coords + t*4);
        int x0 = cbox.x, y0 = cbox.y, x1 = cbox.z, y1 = cbox.w;
        if (y1 == y0) y1 = y0 + 1;
        if (x1 == x0) x1 = x0 + 1;

        const int wx0  = x0 >> 2;                // first 4-px group
        const int wx1  = (x1 + 3) >> 2;          // exclusive
        const int wpr  = wx1 - wx0;              // groups per row
        const int rows = y1 - y0;
        const int nidx = rows * wpr;             // flattened (row, group) space

        const float* clb = cl + (size_t)b * NC * HW;
        int c0=0, c1=0, c2=0, c3=0, c4=0;
        for (int idx = lane; idx < nidx; idx += 64) {
            float4 v[2][NC];
            int    xb[2];
            bool   ok[2];
#pragma unroll
            for (int u = 0; u < 2; ++u) {
                int id = idx + u * 32;
                ok[u] = (id < nidx);
                if (ok[u]) {
                    int ry = id / wpr;
                    int wx = wx0 + (id - ry * wpr);
                    xb[u]  = wx * 4;             // first pixel x of this group
                    size_t p = (size_t)(y0 + ry) * W + (size_t)xb[u];
#pragma unroll
                    for (int c = 0; c < NC; ++c)
                        v[u][c] = *reinterpret_cast<const float4*>(clb + p + (size_t)c * HW);
                }
            }
#pragma unroll
            for (int u = 0; u < 2; ++u) {
                if (ok[u]) {
#pragma unroll
                    for (int j = 0; j < 4; ++j) {
                        int x = xb[u] + j;
                        if (x >= x0 && x < x1) {
                            float p0 = (&v[u][0].x)[j];
                            float p1 = (&v[u][1].x)[j];
                            float p2 = (&v[u][2].x)[j];
                            float p3 = (&v[u][3].x)[j];
                            float p4 = (&v[u][4].x)[j];
                            float best = p0; int lab = 0;
                            if (p1 > best) { best = p1; lab = 1; }
                            if (p2 > best) { best = p2; lab = 2; }
                            if (p3 > best) { best = p3; lab = 3; }
                            if (p4 > best) { best = p4; lab = 4; }
                            c0 += (lab==0); c1 += (lab==1); c2 += (lab==2);
                            c3 += (lab==3); c4 += (lab==4);
                        }
                    }
                }
            }
        }
        c0 = __reduce_add_sync(0xffffffffu, c0);
        c1 = __reduce_add_sync(0xffffffffu, c1);
        c2 = __reduce_add_sync(0xffffffffu, c2);
        c3 = __reduce_add_sync(0xffffffffu, c3);
        c4 = __reduce_add_sync(0xffffffffu, c4);

        if (lane == 0) {
            int maj = 0, bestc = c0;
            if (c1 > bestc) { bestc = c1; maj = 1; }
            if (c2 > bestc) { bestc = c2; maj = 2; }
            if (c3 > bestc) { bestc = c3; maj = 3; }
            if (c4 > bestc) { bestc = c4; maj = 4; }

            float lg[NC];
            lg[0] = acc0 + bc[0]; lg[1] = acc1 + bc[1]; lg[2] = acc2 + bc[2];
            lg[3] = acc3 + bc[3]; lg[4] = acc4 + bc[4];
            float mx = lg[0];
#pragma unroll
            for (int c = 1; c < NC; ++c) mx = fmaxf(mx, lg[c]);
            float se = 0.f;
#pragma unroll
            for (int c = 0; c < NC; ++c) se += expf(lg[c] - mx);
            float nll = -(lg[maj] - mx - logf(se));

            g_nll[t] = nll;
            g_msk[t] = 1;
        }
    } else {
        // masked out: contributes 0 to numerator, 0 to denominator
        if (lane == 0) { g_nll[t] = 0.f; g_msk[t] = 0; }
    }

    // ---- last-block-done deterministic reduction ----
    __shared__ bool s_last;
    __threadfence();
    __syncthreads();
    if (threadIdx.x == 0) {
        s_last = (atomicAdd(&g_ctr, 1) == GRID - 1);
    }
    __syncthreads();
    if (!s_last) return;
    __threadfence();

    __shared__ float sf[THREADS];
    __shared__ int   si[THREADS];
    float a = 0.f; int mm = 0;
#pragma unroll
    for (int i = threadIdx.x; i < NTOK; i += THREADS) {
        a += g_nll[i]; mm += g_msk[i];
    }
    sf[threadIdx.x] = a; si[threadIdx.x] = mm;
    __syncthreads();
#pragma unroll
    for (int s = THREADS/2; s > 0; s >>= 1) {
        if (threadIdx.x < s) { sf[threadIdx.x] += sf[threadIdx.x+s];
                               si[threadIdx.x] += si[threadIdx.x+s]; }
        __syncthreads();
    }
    if (threadIdx.x == 0) {
        out[0] = sf[0] / (float)si[0];
        g_ctr = 0;                 // reset for next graph replay
    }
}

extern "C" void kernel_launch(void* const* d_in, const int* in_sizes, int n_in,
                              void* d_out, int out_size) {
    const float* fuse   = (const float*)d_in[0];   // [8,512,512]
    const float* cl     = (const float*)d_in[1];   // [8,5,768,768]
    const float* Wc     = (const float*)d_in[2];   // [5,512]
    const float* bc     = (const float*)d_in[3];   // [5]
    const int*   coords = (const int*)d_in[4];     // [8,512,4]
    const int*   mask   = (const int*)d_in[5];     // [8,512]
    float* out = (float*)d_out;

    token_kernel<<<GRID, THREADS>>>(cl, fuse, Wc, bc, coords, mask, out);
}